// round 5
// baseline (speedup 1.0000x reference)
#include <cuda_runtime.h>
#include <cstdint>

// CategorySpecificLinear via mma.sync.m16n8k8 TF32 (base sm_103; tcgen05 is
// rejected by this bench's ptxas target).
//
// Round 5: CTA tile 256(M) x 128(N), BK=16, 8 warps (4Mx2N), warp tile 64x64.
// Fragment double-buffering across the 2 k-steps per chunk + cross-chunk frag
// prefetch; staging STS interleaved between MMA blocks. A rows padded to 20
// floats (conflict-free, no swizzle ALU), B rows padded to 136 floats.

#define A_ROWB   80                        // 20 floats per A row
#define STAGE_A  (256 * A_ROWB)            // 20480
#define B_ROWB   544                       // 136 floats per B row
#define STAGE_B  (16 * B_ROWB)             // 8704
#define B_OFF    (2 * STAGE_A)
#define SMEM_DYN (2 * STAGE_A + 2 * STAGE_B)   // 58368

static __device__ __forceinline__ uint32_t f2tf(float f){
    uint32_t r; asm("cvt.rna.tf32.f32 %0, %1;" : "=r"(r) : "f"(f)); return r;
}

static __device__ __forceinline__ void mma_tf32(float d[4],
                                                uint32_t a0, uint32_t a1,
                                                uint32_t a2, uint32_t a3,
                                                uint32_t b0, uint32_t b1){
    asm volatile(
        "mma.sync.aligned.m16n8k8.row.col.f32.tf32.tf32.f32 "
        "{%0,%1,%2,%3}, {%4,%5,%6,%7}, {%8,%9}, {%0,%1,%2,%3};"
        : "+f"(d[0]), "+f"(d[1]), "+f"(d[2]), "+f"(d[3])
        : "r"(a0), "r"(a1), "r"(a2), "r"(a3), "r"(b0), "r"(b1));
}

__global__ __launch_bounds__(256, 1)
void cslin_mma3_kernel(const float* __restrict__ x,
                       const int*   __restrict__ cat_ids,
                       const float* __restrict__ W,
                       const float* __restrict__ bias,
                       float*       __restrict__ y)
{
    constexpr int IDIM = 1024, ODIM = 1024, TDIM = 512;
    extern __shared__ char dsm[];

    const int tid  = threadIdx.x;
    const int wid  = tid >> 5;
    const int lane = tid & 31;
    const int la3  = lane & 3;
    const int lg   = lane >> 2;

    const int n0 = blockIdx.x * 128;
    const int m0 = blockIdx.y * 256;
    const int bb = blockIdx.z;
    const int cat = __ldg(cat_ids + bb);

    const float* xb = x + (size_t)bb  * TDIM * IDIM;
    const float* Wc = W + (size_t)cat * IDIM * ODIM;
    const float* bc = bias + (size_t)cat * ODIM;
    float*       yb = y + (size_t)bb  * TDIM * ODIM;

    // ---- loader geometry ----
    // A chunk 256m x 16k: 4 float4/thread: row = (tid>>2)+64i, col4 = tid&3
    const float* aG = xb + (size_t)(m0 + (tid >> 2)) * IDIM + ((tid & 3) << 2);
    const uint32_t aS = (uint32_t)((tid >> 2) * A_ROWB + (tid & 3) * 16);  // +i*5120
    // B chunk 16k x 128n: 2 float4/thread: row = tid>>4, col = (tid&15)*4 + 64i
    const float* bG = Wc + (size_t)(tid >> 4) * ODIM + n0 + ((tid & 15) << 2);
    const uint32_t bS = (uint32_t)((tid >> 4) * B_ROWB + (tid & 15) * 16);  // +i*256

    // ---- warp tile 64x64 ----
    const int wm = (wid & 3) * 64;
    const int wn = (wid >> 2) * 64;

    uint32_t rA[4];
    #pragma unroll
    for (int i = 0; i < 4; i++) rA[i] = (uint32_t)((wm + i * 16 + lg) * A_ROWB);
    uint32_t bN[8];
    #pragma unroll
    for (int j = 0; j < 8; j++) bN[j] = (uint32_t)((wn + j * 8 + lg) * 4);
    const uint32_t aKoff = (uint32_t)(la3 * 4);     // + ks*32
    const uint32_t bKrow = (uint32_t)(la3 * B_ROWB); // + ks*8 rows = +ks*4352

    float acc[4][8][4];
    #pragma unroll
    for (int i = 0; i < 4; i++)
        #pragma unroll
        for (int j = 0; j < 8; j++)
            #pragma unroll
            for (int q = 0; q < 4; q++) acc[i][j][q] = 0.f;

    uint32_t fa0[16], fb0[16], fa1[16], fb1[16];
    float4 av[4], bv[2];

    // ---- frag load helpers (macros keep indices constant) ----
#define LOAD_FRAGS(FA, FB, STA, STB, KS)                                       \
    do {                                                                       \
        const char* _pb = (STB) + bKrow + (KS) * 4352;                         \
        _Pragma("unroll")                                                      \
        for (int j = 0; j < 8; j++){                                           \
            FB[2*j]   = *(const uint32_t*)(_pb + bN[j]);                       \
            FB[2*j+1] = *(const uint32_t*)(_pb + bN[j] + 4 * B_ROWB);          \
        }                                                                      \
        _Pragma("unroll")                                                      \
        for (int i = 0; i < 4; i++){                                           \
            const char* _pa = (STA) + rA[i] + aKoff + (KS) * 32;               \
            FA[4*i]   = *(const uint32_t*)(_pa);                               \
            FA[4*i+1] = *(const uint32_t*)(_pa + 8 * A_ROWB);                  \
            FA[4*i+2] = *(const uint32_t*)(_pa + 16);                          \
            FA[4*i+3] = *(const uint32_t*)(_pa + 8 * A_ROWB + 16);             \
        }                                                                      \
    } while (0)

#define MMA_BLOCK(FA, FB)                                                      \
    do {                                                                       \
        _Pragma("unroll")                                                      \
        for (int i = 0; i < 4; i++)                                            \
            _Pragma("unroll")                                                  \
            for (int j = 0; j < 8; j++)                                        \
                mma_tf32(acc[i][j], FA[4*i], FA[4*i+1], FA[4*i+2], FA[4*i+3],  \
                         FB[2*j], FB[2*j+1]);                                  \
    } while (0)

#define STAGE_STORE(STA, STB)                                                  \
    do {                                                                       \
        _Pragma("unroll")                                                      \
        for (int i = 0; i < 4; i++)                                            \
            *(uint4*)((STA) + aS + (uint32_t)i * 64 * A_ROWB) =                \
                make_uint4(f2tf(av[i].x), f2tf(av[i].y),                       \
                           f2tf(av[i].z), f2tf(av[i].w));                      \
        _Pragma("unroll")                                                      \
        for (int i = 0; i < 2; i++)                                            \
            *(uint4*)((STB) + bS + (uint32_t)i * 256) =                        \
                make_uint4(f2tf(bv[i].x), f2tf(bv[i].y),                       \
                           f2tf(bv[i].z), f2tf(bv[i].w));                      \
    } while (0)

    // ---- prologue: stage chunk 0 ----
    #pragma unroll
    for (int i = 0; i < 4; i++) av[i] = *(const float4*)(aG + (size_t)(64 * i) * IDIM);
    #pragma unroll
    for (int i = 0; i < 2; i++) bv[i] = *(const float4*)(bG + 64 * i);
    STAGE_STORE(dsm, dsm + B_OFF);
    __syncthreads();
    LOAD_FRAGS(fa0, fb0, dsm, dsm + B_OFF, 0);

    // ---- main loop: 64 K-chunks of 16 ----
    for (int c = 0; c < 64; c++){
        const int s = c & 1;
        char* stA  = dsm + s * STAGE_A;
        char* stB  = dsm + B_OFF + s * STAGE_B;
        char* stAn = dsm + (s ^ 1) * STAGE_A;
        char* stBn = dsm + B_OFF + (s ^ 1) * STAGE_B;

        if (c < 63){
            const int kc = (c + 1) * 16;
            #pragma unroll
            for (int i = 0; i < 4; i++)
                av[i] = *(const float4*)(aG + (size_t)(64 * i) * IDIM + kc);
            #pragma unroll
            for (int i = 0; i < 2; i++)
                bv[i] = *(const float4*)(bG + (size_t)kc * ODIM + 64 * i);
        }

        LOAD_FRAGS(fa1, fb1, stA, stB, 1);   // k-step 1 frags (overlaps MMA ks0)
        MMA_BLOCK(fa0, fb0);                 // k-step 0

        if (c < 63) STAGE_STORE(stAn, stBn); // stage chunk c+1 (LSU while tensor busy)

        MMA_BLOCK(fa1, fb1);                 // k-step 1

        if (c < 63){
            __syncthreads();
            LOAD_FRAGS(fa0, fb0, stAn, stBn, 0);  // prefetch next chunk ks0
        }
    }

    // ---- epilogue: acc + bias -> y ----
    float bias0[8], bias1[8];
    #pragma unroll
    for (int j = 0; j < 8; j++){
        const int gn = n0 + wn + j * 8 + la3 * 2;
        bias0[j] = __ldg(bc + gn);
        bias1[j] = __ldg(bc + gn + 1);
    }
    #pragma unroll
    for (int i = 0; i < 4; i++){
        const int gm = m0 + wm + i * 16 + lg;
        #pragma unroll
        for (int j = 0; j < 8; j++){
            const int gn = n0 + wn + j * 8 + la3 * 2;
            float2 v0 = make_float2(acc[i][j][0] + bias0[j], acc[i][j][1] + bias1[j]);
            float2 v1 = make_float2(acc[i][j][2] + bias0[j], acc[i][j][3] + bias1[j]);
            *(float2*)(yb + (size_t)gm * ODIM + gn)       = v0;
            *(float2*)(yb + (size_t)(gm + 8) * ODIM + gn) = v1;
        }
    }
}

extern "C" void kernel_launch(void* const* d_in, const int* in_sizes, int n_in,
                              void* d_out, int out_size)
{
    const float* x       = (const float*)d_in[0];
    const int*   cat_ids = (const int*)  d_in[1];
    const float* W       = (const float*)d_in[2];
    const float* bias    = (const float*)d_in[3];
    float*       y       = (float*)d_out;

    cudaFuncSetAttribute(cslin_mma3_kernel,
                         cudaFuncAttributeMaxDynamicSharedMemorySize, SMEM_DYN);
    dim3 grid(1024 / 128, 512 / 256, 64);   // (8, 2, 64)
    cslin_mma3_kernel<<<grid, 256, SMEM_DYN>>>(x, cat_ids, W, bias, y);
}